// round 16
// baseline (speedup 1.0000x reference)
#include <cuda_runtime.h>
#include <cuda.h>
#include <cuda_bf16.h>
#include <cuda_fp16.h>
#include <math.h>

#define NN   8192
#define DIM  128
#define NMOL 256
#define OD   56
#define ODP  64

typedef unsigned long long u64;
typedef unsigned int u32;
typedef unsigned short u16;
typedef unsigned char u8;

// ---------------- f32x2 helpers ----------------------------------------------
__device__ __forceinline__ u64 pk2(float lo, float hi) {
    u64 r; asm("mov.b64 %0, {%1,%2};" : "=l"(r) : "f"(lo), "f"(hi)); return r;
}
__device__ __forceinline__ void upk2(u64 v, float &lo, float &hi) {
    asm("mov.b64 {%0,%1}, %2;" : "=f"(lo), "=f"(hi) : "l"(v));
}
__device__ __forceinline__ void fma2(u64 &d, u64 a, u64 b) {
    asm("fma.rn.f32x2 %0, %1, %2, %0;" : "+l"(d) : "l"(a), "l"(b));
}

// ---------------- FMA-only exp ------------------------------------------------
__device__ __forceinline__ float fexp(float x) {
    x = fmaxf(x, -87.0f);
    float y = x * 1.44269504f;
    float r = rintf(y);
    float f = y - r;
    float p = 1.33335581e-3f;
    p = fmaf(p, f, 9.61812911e-3f);
    p = fmaf(p, f, 5.55041087e-2f);
    p = fmaf(p, f, 2.40226507e-1f);
    p = fmaf(p, f, 6.93147181e-1f);
    p = fmaf(p, f, 1.0f);
    int e = (int)r;
    return p * __int_as_float((e + 127) << 23);
}

__device__ __forceinline__ u32 encf(float s) {
    u32 b = __float_as_uint(s);
    return (b & 0x80000000u) ? ~b : (b | 0x80000000u);
}
__device__ __forceinline__ float decf(u32 u) {
    return __uint_as_float((u & 0x80000000u) ? (u & 0x7fffffffu) : ~u);
}

// ---------------- MMA / ldmatrix helpers --------------------------------------
__device__ __forceinline__ u32 smem_u32(const void* p) {
    return (u32)__cvta_generic_to_shared(p);
}
__device__ __forceinline__ void ldm_x4(u32 a, u32* r) {
    asm volatile("ldmatrix.sync.aligned.m8n8.x4.shared.b16 {%0,%1,%2,%3}, [%4];"
        : "=r"(r[0]), "=r"(r[1]), "=r"(r[2]), "=r"(r[3]) : "r"(a));
}
__device__ __forceinline__ void mma_s8(int* c, const u32* a, const u32* b) {
    asm volatile(
        "mma.sync.aligned.m16n8k32.row.col.s32.s8.s8.s32 "
        "{%0,%1,%2,%3}, {%4,%5,%6,%7}, {%8,%9}, {%0,%1,%2,%3};"
        : "+r"(c[0]), "+r"(c[1]), "+r"(c[2]), "+r"(c[3])
        : "r"(a[0]), "r"(a[1]), "r"(a[2]), "r"(a[3]), "r"(b[0]), "r"(b[1]));
}

// ---------------- TMA / mbarrier ----------------------------------------------
__device__ __forceinline__ void tma2d(u32 dst, const void* map, int x, int y, u32 mbar) {
    asm volatile(
        "cp.async.bulk.tensor.2d.shared::cta.global.tile.mbarrier::complete_tx::bytes "
        "[%0], [%1, {%2, %3}], [%4];"
        :: "r"(dst), "l"(map), "r"(x), "r"(y), "r"(mbar) : "memory");
}
__device__ __forceinline__ void mbar_init(u32 a, u32 cnt) {
    asm volatile("mbarrier.init.shared.b64 [%0], %1;" :: "r"(a), "r"(cnt) : "memory");
}
__device__ __forceinline__ void mbar_expect(u32 a, u32 bytes) {
    asm volatile("mbarrier.arrive.expect_tx.shared.b64 _, [%0], %1;"
                 :: "r"(a), "r"(bytes) : "memory");
}
__device__ __forceinline__ void mbar_wait(u32 a, u32 parity) {
    asm volatile(
        "{\n\t.reg .pred P;\n\t"
        "W_%=:\n\t"
        "mbarrier.try_wait.parity.acquire.cta.shared::cta.b64 P, [%0], %1, 0x989680;\n\t"
        "@P bra.uni D_%=;\n\t"
        "bra.uni W_%=;\n\t"
        "D_%=:\n\t}"
        :: "r"(a), "r"(parity) : "memory");
}
__device__ __forceinline__ void mbar_inval(u32 a) {
    asm volatile("mbarrier.inval.shared.b64 [%0];" :: "r"(a) : "memory");
}
__device__ __forceinline__ u32 swz(u32 o) { return o ^ ((o >> 3) & 0x70); }

// ---------------- scratch -----------------------------------------------------
__device__ u8 g_adj8[(size_t)NN * NN];
__device__ u8 g_h8T[(size_t)DIM * NN];
__device__ float g_x [NN * DIM];
__device__ float g_h [NN * DIM];
__device__ float g_t [NN * DIM];
__device__ float g_z [NN * DIM];
__device__ float g_s1[NN];
__device__ float g_s2[NN];
__device__ u32   g_s2maxu;
__device__ float g_pa[NN], g_pb[NN];
__device__ float2 g_egq[NN];
__device__ float g_ho [NN * ODP];
__device__ float g_a56[NN * ODP];
__device__ float g_wpad[DIM * ODP];
__device__ float g_cm[DIM];
__device__ u32   g_cmxu[2][DIM];

// ---------------- small utility kernels ---------------------------------------
__global__ void k_gather(const int* __restrict__ fp, const float* __restrict__ emb) {
    int idx = blockIdx.x * 256 + threadIdx.x;
    if (blockIdx.x == 0 && threadIdx.x < DIM) {
        g_cmxu[0][threadIdx.x] = 0u;
        g_cmxu[1][threadIdx.x] = 0u;
    }
    int i = idx >> 7, c = idx & 127;
    g_x[idx] = emb[fp[i] * DIM + c];
}

__global__ void k_padw(const float* __restrict__ W) {
    int idx = blockIdx.x * 256 + threadIdx.x;
    int k = idx >> 6, c = idx & 63;
    g_wpad[idx] = (c < OD) ? W[k * OD + c] : 0.0f;
}

__global__ void k_adjconv(const float* __restrict__ adj) {
    size_t base = ((size_t)blockIdx.x * 256 + threadIdx.x) * 8;
    float4 a = *(const float4*)(adj + base);
    float4 b = *(const float4*)(adj + base + 4);
    u8 o[8];
    o[0] = a.x != 0.f ? 1 : 0; o[1] = a.y != 0.f ? 1 : 0;
    o[2] = a.z != 0.f ? 1 : 0; o[3] = a.w != 0.f ? 1 : 0;
    o[4] = b.x != 0.f ? 1 : 0; o[5] = b.y != 0.f ? 1 : 0;
    o[6] = b.z != 0.f ? 1 : 0; o[7] = b.w != 0.f ? 1 : 0;
    *(u64*)(g_adj8 + base) = *(u64*)o;
}

// H [NN][ldf] fp32 -> H^T s8, per-column quant from raw cmxu[par]
__global__ void __launch_bounds__(256) k_transp8i(const float* __restrict__ H, int ldf,
                                                  int par) {
    __shared__ float S[64][65];
    const int n0 = blockIdx.x * 64, f0 = blockIdx.y * 64;
    const int t = threadIdx.x, r = t >> 2, cb = t & 3;
#pragma unroll
    for (int q = 0; q < 4; q++) {
        float4 v = *(const float4*)&H[(size_t)(n0 + r) * ldf + f0 + cb * 16 + q * 4];
        S[r][cb * 16 + q * 4 + 0] = v.x; S[r][cb * 16 + q * 4 + 1] = v.y;
        S[r][cb * 16 + q * 4 + 2] = v.z; S[r][cb * 16 + q * 4 + 3] = v.w;
    }
    __syncthreads();
    const int f = t >> 2, nb = t & 3;
    float cmx = __uint_as_float(g_cmxu[par][f0 + f]);
    const float si = (cmx > 0.f) ? 127.0f / cmx : 0.f;
    char o[16];
#pragma unroll
    for (int q = 0; q < 16; q++) {
        float v = S[nb * 16 + q][f] * si;
        v = fminf(fmaxf(v, -127.f), 127.f);
        o[q] = (char)__float2int_rn(v);
    }
    *(uint4*)(g_h8T + (size_t)(f0 + f) * NN + n0 + nb * 16) = *(uint4*)o;
}

// ---------------- row L2-normalize --------------------------------------------
__global__ void k_l2norm(const float* __restrict__ in, float* __restrict__ out) {
    int w = threadIdx.x >> 5, lane = threadIdx.x & 31;
    int row = blockIdx.x * 8 + w;
    const float* r = in + (size_t)row * DIM;
    float v[4], ss = 0.f;
#pragma unroll
    for (int q = 0; q < 4; q++) { v[q] = r[lane + q * 32]; ss += v[q] * v[q]; }
#pragma unroll
    for (int o = 16; o > 0; o >>= 1) ss += __shfl_xor_sync(0xffffffffu, ss, o);
    float inv = 1.0f / fmaxf(sqrtf(ss), 1e-12f);
#pragma unroll
    for (int q = 0; q < 4; q++) out[(size_t)row * DIM + lane + q * 32] = v[q] * inv;
}

// ---------------- s1/s2 projections + global s2 max ---------------------------
__global__ void k_s12(const float* __restrict__ H, int ld, int Dr,
                      const float* __restrict__ a) {
    int w = threadIdx.x >> 5, lane = threadIdx.x & 31;
    int row = blockIdx.x * 8 + w;
    const float* r = H + (size_t)row * ld;
    float p1 = 0.f, p2 = 0.f;
    for (int c = lane; c < Dr; c += 32) {
        float v = r[c];
        p1 = fmaf(v, a[c], p1);
        p2 = fmaf(v, a[Dr + c], p2);
    }
#pragma unroll
    for (int o = 16; o > 0; o >>= 1) {
        p1 += __shfl_xor_sync(0xffffffffu, p1, o);
        p2 += __shfl_xor_sync(0xffffffffu, p2, o);
    }
    if (lane == 0) {
        g_s1[row] = p1; g_s2[row] = p2;
        atomicMax(&g_s2maxu, encf(p2));
    }
}

// ---------------- attention precompute ----------------------------------------
__global__ void k_prep() {
    int i = blockIdx.x * 256 + threadIdx.x;
    float gmax = decf(g_s2maxu);
    float s1 = g_s1[i], s2 = g_s2[i];
    float u = s1 + gmax;
    float m = (u > 0.f) ? u : 0.25f * u;
    g_pa[i] = 127.0f * fexp(s1 - m);
    g_pb[i] = 127.0f * fexp(0.25f * s1 - m);
    float2 e; e.x = fexp(s2); e.y = fexp(0.25f * s2);
    g_egq[i] = e;
}

// ================== TMA-fed s8 mma.sync kernel (32 x NB*64 per CTA) ===========
// grid (NN/32, 1). Chunk = 128 K. Warps: 2 in M x 4 in N (16 x NB*16 each).
// MODE 0: Out = resid + (adj @ Hq) * colscale                 (s32 exact)
// MODE 1: q_ij = rint(adj_ij * max(a_i*eg_j, b_i*eq_j)) s8;
//         d_i via ones-column MMA, 4-way kk-split (exact);
//         Out_i = elu((q@Hq)*colscale / d_i), opt accumulate.
#define TNST 4
struct TAux {
    u8 Phi[2][32][144];
    float A[32], B[32], D[4][32];
    u64 bar[TNST];
};

template<int NB, int MODE>
__global__ void __launch_bounds__(256) k_tmma(
    const __grid_constant__ CUtensorMap mAdj,
    const __grid_constant__ CUtensorMap mH,
    const float* __restrict__ resid,
    float* __restrict__ Out, int ldo, int accum, int par)
{
    constexpr int BK = 128, NT = NN / BK;
    constexpr int FN = NB * 2;                  // n8 frags per warp
    constexpr u32 STAGE_B = 4096 + NB * 8192;   // adj(32x128) + NB H(64x128)

    extern __shared__ char raw[];
    TAux& X = *reinterpret_cast<TAux*>(raw);
    const u32 tiles_u = (smem_u32(raw) + (u32)sizeof(TAux) + 1023u) & ~1023u;
    char* tiles_p = raw + (tiles_u - smem_u32(raw));

    const int t = threadIdx.x, lane = t & 31, warp = t >> 5;
    const int i0 = blockIdx.x * 32;
    const int wm = warp >> 2, wn = warp & 3;    // 2 x 4 warp grid
    const int pr = warp * 4 + (lane >> 3);      // P-gen row (0..31)
    const int pc = (lane & 7) * 16;             // P-gen byte-col start

    if (MODE && t < 32) { X.A[t] = g_pa[i0 + t]; X.B[t] = g_pb[i0 + t]; }
    if (t == 0)
        for (int s = 0; s < TNST; s++) mbar_init(smem_u32(&X.bar[s]), 1);
    __syncthreads();
    float ai = 0.f, bi = 0.f;
    if (MODE) { ai = X.A[pr]; bi = X.B[pr]; }

    if (t == 0) {
#pragma unroll
        for (int s = 0; s < 3; s++) {
            u32 bar = smem_u32(&X.bar[s]);
            mbar_expect(bar, STAGE_B);
            u32 st = tiles_u + s * STAGE_B;
            tma2d(st, &mAdj, s * 128, i0, bar);
#pragma unroll
            for (int b = 0; b < NB; b++)
                tma2d(st + 4096 + b * 8192, &mH, s * 128, b * 64, bar);
        }
    }

    int iacc[FN][4];
    int dacc[4];
#pragma unroll
    for (int b = 0; b < FN; b++)
#pragma unroll
        for (int c = 0; c < 4; c++) iacc[b][c] = 0;
#pragma unroll
    for (int c = 0; c < 4; c++) dacc[c] = 0;
    const u32 bones = (lane < 4) ? 0x01010101u : 0u;
    u32 bh1[2] = { bones, bones };

    for (int kt = 0; kt < NT; kt++) {
        const int cur = kt & 3, k0 = kt * BK;
        const u32 stg = tiles_u + cur * STAGE_B;
        mbar_wait(smem_u32(&X.bar[cur]), (kt >> 2) & 1);

        if (MODE) {
            const int pb = kt & 1;
            const char* adjp = tiles_p + cur * STAGE_B;
            u32 off = (u32)pr * 128 + (u32)pc;
            uint4 av = *(const uint4*)(adjp + swz(off));
            u8 ab[16];
            *(uint4*)ab = av;
            char pq[16];
            const float2* egq = g_egq + k0 + pc;
#pragma unroll
            for (int c = 0; c < 16; c++) {
                float2 e = egq[c];
                float p = fmaxf(ai * e.x, bi * e.y);
                p = ab[c] ? p : 0.f;
                pq[c] = (char)__float2int_rn(p);
            }
            *(uint4*)&X.Phi[pb][pr][pc] = *(uint4*)pq;
        }
        __syncthreads();  // Phi(kt) ready AND all warps completed chunk kt-1

        if (t == 0 && kt + 3 < NT) {
            const int s = (kt + 3) & 3;
            u32 bar = smem_u32(&X.bar[s]);
            mbar_expect(bar, STAGE_B);
            u32 st = tiles_u + s * STAGE_B;
            tma2d(st, &mAdj, (kt + 3) * 128, i0, bar);
#pragma unroll
            for (int b = 0; b < NB; b++)
                tma2d(st + 4096 + b * 8192, &mH, (kt + 3) * 128, b * 64, bar);
        }

#pragma unroll
        for (int kk = 0; kk < 4; kk++) {
            u32 ah[4];
            {
                int rr = wm * 16 + (lane & 15);
                u32 boff = (u32)kk * 32 + ((u32)(lane >> 4)) * 16;
                u32 a = MODE ? smem_u32(&X.Phi[kt & 1][rr][0]) + boff
                             : stg + swz((u32)rr * 128 + boff);
                ldm_x4(a, ah);
            }
            u32 bh[FN][2];
#pragma unroll
            for (int fp2 = 0; fp2 < NB; fp2++) {
                int nb = wn * (NB * 16) + fp2 * 16;
                u32 rowN = (u32)nb + (u32)(lane & 7) + (((u32)lane >> 4) << 3);
                u32 a = stg + 4096 + (rowN >> 6) * 8192
                      + swz((rowN & 63) * 128 + (u32)kk * 32 + (((u32)lane >> 3) & 1) * 16);
                u32 r4[4];
                ldm_x4(a, r4);
                bh[2*fp2][0] = r4[0]; bh[2*fp2][1] = r4[1];
                bh[2*fp2+1][0] = r4[2]; bh[2*fp2+1][1] = r4[3];
            }
#pragma unroll
            for (int fn = 0; fn < FN; fn++)
                mma_s8(iacc[fn], ah, bh[fn]);
            if (MODE && kk == wn)           // 4-way balanced d-MMA
                mma_s8(dacc, ah, bh1);
        }
        if (!MODE) __syncthreads();   // stage-reuse guard (MODE1 uses P-gen sync)
    }

    if (MODE && (lane & 3) == 0) {
        X.D[wn][wm * 16 + (lane >> 2)]     = (float)dacc[0];
        X.D[wn][wm * 16 + (lane >> 2) + 8] = (float)dacc[2];
    }
    __syncthreads();

#pragma unroll
    for (int h = 0; h < 2; h++) {
        int rl = wm * 16 + (lane >> 2) + h * 8;
        int row = i0 + rl;
#pragma unroll
        for (int fn = 0; fn < FN; fn++) {
            int col = wn * (NB * 16) + fn * 8 + (lane & 3) * 2;
            float sc0 = __uint_as_float(g_cmxu[par][col])     * (1.0f / 127.0f);
            float sc1 = __uint_as_float(g_cmxu[par][col + 1]) * (1.0f / 127.0f);
            float* op = Out + (size_t)row * ldo + col;
            if (MODE == 0) {
                float v0 = (float)iacc[fn][2 * h]     * sc0;
                float v1 = (float)iacc[fn][2 * h + 1] * sc1;
                float2 rr = *(const float2*)(resid + (size_t)row * ldo + col);
                float2 o; o.x = v0 + rr.x; o.y = v1 + rr.y;
                *(float2*)op = o;
            } else {
                float dd = X.D[0][rl] + X.D[1][rl] + X.D[2][rl] + X.D[3][rl];
                float v0, v1;
                if (dd > 0.f) {
                    float inv = 1.0f / dd;
                    v0 = (float)iacc[fn][2 * h]     * sc0 * inv;
                    v1 = (float)iacc[fn][2 * h + 1] * sc1 * inv;
                } else { v0 = g_cm[col]; v1 = g_cm[col + 1]; }
                v0 = (v0 > 0.f) ? v0 : fexp(v0) - 1.0f;
                v1 = (v1 > 0.f) ? v1 : fexp(v1) - 1.0f;
                if (accum) {
                    float2 zz = *(const float2*)op;
                    v0 += zz.x; v1 += zz.y;
                }
                float2 o; o.x = v0; o.y = v1;
                *(float2*)op = o;
            }
        }
    }
    __syncthreads();
    if (t == 0)
        for (int s = 0; s < TNST; s++) mbar_inval(smem_u32(&X.bar[s]));
}

// ---------------- dense GEMM + fused column abs-max (parity-buffered) ---------
__global__ void __launch_bounds__(256) k_gemm(
        const float* __restrict__ A,
        const float* __restrict__ B, int ldb,
        const float* __restrict__ bias,
        float* __restrict__ C, int ldc,
        float scale, int relu, int rst, int par)
{
    extern __shared__ float sm[];
    float (*As)[68] = (float(*)[68])sm;
    float (*Bs)[68] = (float(*)[68])(sm + 128 * 68);
    const int t = threadIdx.x;
    const int row0 = blockIdx.x * 64, co = blockIdx.y * 64;

    if (blockIdx.x == 0 && blockIdx.y == 0) {
        if (rst && t == 0) g_s2maxu = 0u;
        if (t < DIM) g_cmxu[par ^ 1][t] = 0u;
    }

#pragma unroll
    for (int l = 0; l < 8; l++) {
        int u = t + l * 256;
        int m = u >> 5, kq = (u & 31) * 4;
        float4 v = *(const float4*)&A[(size_t)(row0 + m) * DIM + kq];
        As[kq + 0][m] = v.x; As[kq + 1][m] = v.y;
        As[kq + 2][m] = v.z; As[kq + 3][m] = v.w;
    }
#pragma unroll
    for (int l = 0; l < 8; l++) {
        int u = t + l * 256;
        int k = u >> 4, c = (u & 15) * 4;
        *(float4*)&Bs[k][c] = *(const float4*)&B[(size_t)k * ldb + co + c];
    }
    __syncthreads();

    const int tx = t & 15, ty = t >> 4;
    u64 acc[4][2];
#pragma unroll
    for (int i = 0; i < 4; i++) { acc[i][0] = 0ULL; acc[i][1] = 0ULL; }

#pragma unroll 4
    for (int k = 0; k < 128; k++) {
        float4 a4 = *(const float4*)&As[k][ty * 4];
        u64 b0 = *(const u64*)&Bs[k][tx * 4];
        u64 b1 = *(const u64*)&Bs[k][tx * 4 + 2];
        fma2(acc[0][0], pk2(a4.x, a4.x), b0); fma2(acc[0][1], pk2(a4.x, a4.x), b1);
        fma2(acc[1][0], pk2(a4.y, a4.y), b0); fma2(acc[1][1], pk2(a4.y, a4.y), b1);
        fma2(acc[2][0], pk2(a4.z, a4.z), b0); fma2(acc[2][1], pk2(a4.z, a4.z), b1);
        fma2(acc[3][0], pk2(a4.w, a4.w), b0); fma2(acc[3][1], pk2(a4.w, a4.w), b1);
    }
    float tmax[4] = {0.f, 0.f, 0.f, 0.f};
#pragma unroll
    for (int i = 0; i < 4; i++) {
        int m = row0 + ty * 4 + i;
#pragma unroll
        for (int j = 0; j < 2; j++) {
            int c = co + tx * 4 + 2 * j;
            float lo, hi; upk2(acc[i][j], lo, hi);
            float v0 = scale * lo, v1 = scale * hi;
            if (bias)  { v0 += bias[c]; v1 += bias[c + 1]; }
            if (relu)  { v0 = fmaxf(v0, 0.f); v1 = fmaxf(v1, 0.f); }
            tmax[2 * j]     = fmaxf(tmax[2 * j],     fabsf(v0));
            tmax[2 * j + 1] = fmaxf(tmax[2 * j + 1], fabsf(v1));
            float2 o; o.x = v0; o.y = v1;
            *(float2*)&C[(size_t)m * ldc + c] = o;
        }
    }
    __syncthreads();
    float* red = sm;
#pragma unroll
    for (int q = 0; q < 4; q++) red[ty * 64 + tx * 4 + q] = tmax[q];
    __syncthreads();
    if (t < 64) {
        float m = 0.f;
#pragma unroll
        for (int k = 0; k < 16; k++) m = fmaxf(m, red[k * 64 + t]);
        atomicMax(&g_cmxu[par][co + t], __float_as_uint(m));
    }
}

// ---------------- row softmax over first 56 of 64 cols ------------------------
__global__ void k_smax56(float* __restrict__ X) {
    int w = threadIdx.x >> 5, lane = threadIdx.x & 31;
    int row = blockIdx.x * 8 + w;
    float* r = X + (size_t)row * ODP;
    float v0 = (lane < OD)      ? r[lane]      : -3e38f;
    float v1 = (lane + 32 < OD) ? r[lane + 32] : -3e38f;
    float m = fmaxf(v0, v1);
#pragma unroll
    for (int o = 16; o > 0; o >>= 1) m = fmaxf(m, __shfl_xor_sync(0xffffffffu, m, o));
    float e0 = (lane < OD)      ? fexp(v0 - m) : 0.f;
    float e1 = (lane + 32 < OD) ? fexp(v1 - m) : 0.f;
    float s = e0 + e1;
#pragma unroll
    for (int o = 16; o > 0; o >>= 1) s += __shfl_xor_sync(0xffffffffu, s, o);
    float inv = 1.0f / s;
    if (lane < OD)      r[lane]      = e0 * inv;
    if (lane + 32 < OD) r[lane + 32] = e1 * inv;
}

// ---------------- segment-sum readout + MLP head ------------------------------
__global__ void k_head(const int* __restrict__ seg,
                       const float* __restrict__ Wout, const float* __restrict__ bout,
                       const float* __restrict__ Wprop, const float* __restrict__ bprop,
                       float* __restrict__ out)
{
    __shared__ float v[OD];
    __shared__ float o[OD];
    __shared__ int bnd[2];
    const int m = blockIdx.x, t = threadIdx.x;
    if (t < 2) {
        int target = m + t;
        int lo = 0, hi = NN;
        while (lo < hi) { int mid = (lo + hi) >> 1; if (seg[mid] < target) lo = mid + 1; else hi = mid; }
        bnd[t] = lo;
    }
    __syncthreads();
    int lo = bnd[0], hi = bnd[1];
    if (t < OD) {
        float s = 0.f;
        for (int i = lo; i < hi; i++) s += g_a56[(size_t)i * ODP + t];
        v[t] = s;
    }
    __syncthreads();
    for (int l = 0; l < 2; l++) {
        if (t < OD) {
            float s = bout[l * OD + t];
            const float* W = Wout + l * OD * OD;
            for (int k = 0; k < OD; k++) s = fmaf(v[k], W[k * OD + t], s);
            o[t] = fmaxf(s, 0.f);
        }
        __syncthreads();
        if (t < OD) v[t] = o[t];
        __syncthreads();
    }
    if (t < 2) {
        float s = bprop[t];
        for (int k = 0; k < OD; k++) s = fmaf(v[k], Wprop[k * 2 + t], s);
        float r;
        if (s >= 0.f) r = 1.0f / (1.0f + fexp(-s));
        else { float e = fexp(s); r = e / (1.0f + e); }
        out[m * 2 + t] = r;
    }
}

// ---------------- orchestration ----------------------------------------------
typedef CUresult (*tmap_fn_t)(CUtensorMap*, CUtensorMapDataType, cuuint32_t, void*,
                              const cuuint64_t*, const cuuint64_t*, const cuuint32_t*,
                              const cuuint32_t*, CUtensorMapInterleave, CUtensorMapSwizzle,
                              CUtensorMapL2promotion, CUtensorMapFloatOOBfill);

static void make_tmap8(tmap_fn_t fn, CUtensorMap* m, void* base,
                       unsigned long long d0, unsigned long long d1, unsigned box1) {
    cuuint64_t dims[2] = { d0, d1 };
    cuuint64_t strides[1] = { d0 };
    cuuint32_t box[2] = { 128, box1 };
    cuuint32_t es[2] = { 1, 1 };
    fn(m, CU_TENSOR_MAP_DATA_TYPE_UINT8, 2, base, dims, strides, box, es,
       CU_TENSOR_MAP_INTERLEAVE_NONE, CU_TENSOR_MAP_SWIZZLE_128B,
       CU_TENSOR_MAP_L2_PROMOTION_L2_128B, CU_TENSOR_MAP_FLOAT_OOB_FILL_NONE);
}

extern "C" void kernel_launch(void* const* d_in, const int* in_sizes, int n_in,
                              void* d_out, int out_size) {
    const int*   fp   = (const int*)  d_in[0];
    const float* adj  = (const float*)d_in[1];
    const int*   seg  = (const int*)  d_in[2];
    const float* emb  = (const float*)d_in[3];
    const float* Wfp  = (const float*)d_in[4];
    const float* bfp  = (const float*)d_in[5];
    const float* Wh   = (const float*)d_in[6];
    const float* ah   = (const float*)d_in[7];
    const float* Woa  = (const float*)d_in[8];
    const float* aoa  = (const float*)d_in[9];
    const float* Wout = (const float*)d_in[10];
    const float* bout = (const float*)d_in[11];
    const float* Wpr  = (const float*)d_in[12];
    const float* bpr  = (const float*)d_in[13];
    float* out = (float*)d_out;

    float *x, *h, *tb, *z, *ho, *a56, *wpad;
    void *adj8_p, *h8T_p;
    cudaGetSymbolAddress((void**)&x,    g_x);
    cudaGetSymbolAddress((void**)&h,    g_h);
    cudaGetSymbolAddress((void**)&tb,   g_t);
    cudaGetSymbolAddress((void**)&z,    g_z);
    cudaGetSymbolAddress((void**)&ho,   g_ho);
    cudaGetSymbolAddress((void**)&a56,  g_a56);
    cudaGetSymbolAddress((void**)&wpad, g_wpad);
    cudaGetSymbolAddress(&adj8_p, g_adj8);
    cudaGetSymbolAddress(&h8T_p,  g_h8T);

    tmap_fn_t tmap_fn = nullptr;
    cudaDriverEntryPointQueryResult qr;
    cudaGetDriverEntryPointByVersion("cuTensorMapEncodeTiled", (void**)&tmap_fn,
                                     12000, cudaEnableDefault, &qr);
    static CUtensorMap mapAdj, mapHT, mapHT64;
    make_tmap8(tmap_fn, &mapAdj,  adj8_p, NN, NN,  32);
    make_tmap8(tmap_fn, &mapHT,   h8T_p,  NN, DIM, 64);
    make_tmap8(tmap_fn, &mapHT64, h8T_p,  NN, 64,  64);

    const int SZT2 = (int)sizeof(TAux) + 1024 + TNST * (4096 + 2 * 8192);
    const int SZT1 = (int)sizeof(TAux) + 1024 + TNST * (4096 + 1 * 8192);
    const int SZG  = 128 * 68 * 2 * 4;
    cudaFuncSetAttribute(k_tmma<2,0>, cudaFuncAttributeMaxDynamicSharedMemorySize, SZT2);
    cudaFuncSetAttribute(k_tmma<2,1>, cudaFuncAttributeMaxDynamicSharedMemorySize, SZT2);
    cudaFuncSetAttribute(k_tmma<1,1>, cudaFuncAttributeMaxDynamicSharedMemorySize, SZT1);
    cudaFuncSetAttribute(k_gemm,      cudaFuncAttributeMaxDynamicSharedMemorySize, SZG);

    k_gather<<<NN * DIM / 256, 256>>>(fp, emb);
    k_adjconv<<<(size_t)NN * NN / 2048, 256>>>(adj);
    k_padw<<<DIM * ODP / 256, 256>>>(Woa);

    int par = 0;
    // 3 message-passing layers
    for (int l = 0; l < 3; l++) {
        k_gemm<<<dim3(NN / 64, 2), 256, SZG>>>(x, Wfp + l * DIM * DIM, DIM,
                                               bfp + l * DIM, h, DIM, 1.f, 1, 0, par);
        k_transp8i<<<dim3(NN / 64, DIM / 64), 256>>>(h, DIM, par);
        k_tmma<2,0><<<NN / 32, 256, SZT2>>>(mapAdj, mapHT, h, tb, DIM, 0, par);
        k_l2norm<<<NN / 8, 256>>>(tb, x);
        par ^= 1;
    }

    // 2 GAT heads
    for (int hd = 0; hd < 2; hd++) {
        k_gemm<<<dim3(NN / 64, 2), 256, SZG>>>(x, Wh + hd * DIM * DIM, DIM,
                                               nullptr, h, DIM, 1.f, 0, 1, par);
        k_s12<<<NN / 8, 256>>>(h, DIM, DIM, ah + hd * 2 * DIM);
        k_prep<<<NN / 256, 256>>>();
        k_transp8i<<<dim3(NN / 64, DIM / 64), 256>>>(h, DIM, par);
        k_tmma<2,1><<<NN / 32, 256, SZT2>>>(mapAdj, mapHT, nullptr, z, DIM, hd, par);
        par ^= 1;
    }

    // out-attention at D=56 (padded to 64); x = z/2 folded into scale
    k_gemm<<<dim3(NN / 64, 1), 256, SZG>>>(z, wpad, ODP, nullptr, ho, ODP, 0.5f, 0, 1, par);
    k_s12<<<NN / 8, 256>>>(ho, ODP, OD, aoa);
    k_prep<<<NN / 256, 256>>>();
    k_transp8i<<<dim3(NN / 64, 1), 256>>>(ho, ODP, par);
    k_tmma<1,1><<<NN / 32, 256, SZT1>>>(mapAdj, mapHT64, nullptr, a56, ODP, 0, par);

    k_smax56<<<NN / 8, 256>>>(a56);
    k_head<<<NMOL, 64>>>(seg, Wout, bout, Wpr, bpr, out);
}